// round 17
// baseline (speedup 1.0000x reference)
#include <cuda_runtime.h>
#include <cuda_fp16.h>
#include <math.h>
#include <stdint.h>

#define B_  4
#define L_  2048
#define IN_ 1024
#define D_  512
#define DI  1024
#define DS  128
#define HD  64
#define KC  4
#define NH  16
#define CD  1280
#define DP  2320
#define NL  2
#define NC  2
#define M_  (B_*L_)   // 8192

// ---------------- scratch (static device globals; no runtime alloc) ------------
__device__ float g_h  [M_*D_];
__device__ float g_zx [M_*DP];
__device__ float g_xbc[M_*CD];
__device__ float g_dt [M_*NH];
__device__ float g_dA [M_*NH];
__device__ float g_y  [M_*DI];

// fp16 packed (2 half per uint32, consecutive k). Activations: hi+lo split.
__device__ uint32_t g_xH [M_*IN_/2], g_xL [M_*IN_/2];
__device__ uint32_t g_uH [M_*D_/2],  g_uL [M_*D_/2];
__device__ uint32_t g_yH [M_*DI/2],  g_yL [M_*DI/2];
// Weights: single fp16
__device__ uint32_t g_w1F[D_*IN_/2];
__device__ uint32_t g_wiF[NL*DP*D_/2];
__device__ uint32_t g_woF[NL*D_*DI/2];

// ---------------- helpers ------------------------------------------------------
__device__ __forceinline__ float silu_f(float x) {
    return x / (1.f + __expf(-x));
}
__device__ __forceinline__ void pack_hl16(float x0, float x1, uint32_t& H, uint32_t& L) {
    __half h0 = __float2half_rn(x0);
    __half h1 = __float2half_rn(x1);
    __half l0 = __float2half_rn(x0 - __half2float(h0));
    __half l1 = __float2half_rn(x1 - __half2float(h1));
    H = (uint32_t)__half_as_ushort(h0) | ((uint32_t)__half_as_ushort(h1) << 16);
    L = (uint32_t)__half_as_ushort(l0) | ((uint32_t)__half_as_ushort(l1) << 16);
}
__device__ __forceinline__ uint32_t pack_f16(float x0, float x1) {
    __half h0 = __float2half_rn(x0);
    __half h1 = __float2half_rn(x1);
    return (uint32_t)__half_as_ushort(h0) | ((uint32_t)__half_as_ushort(h1) << 16);
}
__device__ __forceinline__ void mma_f16(float c[4], const uint32_t a[4], const uint32_t b[2]) {
    asm volatile(
        "mma.sync.aligned.m16n8k16.row.col.f32.f16.f16.f32 "
        "{%0,%1,%2,%3}, {%4,%5,%6,%7}, {%8,%9}, {%0,%1,%2,%3};"
        : "+f"(c[0]), "+f"(c[1]), "+f"(c[2]), "+f"(c[3])
        : "r"(a[0]), "r"(a[1]), "r"(a[2]), "r"(a[3]), "r"(b[0]), "r"(b[1]));
}
__device__ __forceinline__ uint32_t smem_u32(const void* p) {
    uint32_t a;
    asm("{ .reg .u64 t; cvta.to.shared.u64 t, %1; cvt.u32.u64 %0, t; }"
        : "=r"(a) : "l"(p));
    return a;
}
__device__ __forceinline__ void ldsm4(uint32_t* r, uint32_t addr) {
    asm volatile("ldmatrix.sync.aligned.m8n8.x4.shared.b16 {%0,%1,%2,%3}, [%4];"
                 : "=r"(r[0]), "=r"(r[1]), "=r"(r[2]), "=r"(r[3]) : "r"(addr));
}

// ---------------- converters ---------------------------------------------------
__global__ void cvt_a(const float* __restrict__ s, uint32_t* __restrict__ H,
                      uint32_t* __restrict__ L, int npairs)
{
    const int i = blockIdx.x * blockDim.x + threadIdx.x;
    if (i >= npairs) return;
    const float2 v = ((const float2*)s)[i];
    uint32_t h, l;
    pack_hl16(v.x, v.y, h, l);
    H[i] = h; L[i] = l;
}
__global__ void cvt_w(const float* __restrict__ s, uint32_t* __restrict__ F, int npairs)
{
    const int i = blockIdx.x * blockDim.x + threadIdx.x;
    if (i >= npairs) return;
    const float2 v = ((const float2*)s)[i];
    F[i] = pack_f16(v.x, v.y);
}

// ---------------- ldmatrix fp16 2-term tensor-core GEMM ------------------------
// C[M,N] = A[M,K] @ W[N,K]^T.  A split hi/lo fp16 (a = aH + aL); W single fp16.
// acc += aH*W + aL*W  (exact in A to 22 bits; B rounding ~2^-12).
// BM=BN=128, BK=32 elems (16 u32 = 4 chunks of 16B per row). 8 warps, 64x32 each.
// Swizzle: physical chunk = logical chunk ^ ((row>>1)&3) (conflict-free, in-bounds).
// EPI: 0 none, 1 +bias+GELU, 2 +residual.
template<int EPI>
__global__ __launch_bounds__(256, 1) void gemm_ls(
    const uint32_t* __restrict__ AH, const uint32_t* __restrict__ AL,
    const uint32_t* __restrict__ WF,
    const float* __restrict__ bias, const float* __restrict__ res,
    float* __restrict__ C, int M, int N, int Kd)
{
    __shared__ uint32_t sm[3][128 * 16];

    const int tid  = threadIdx.x;
    const int lane = tid & 31, warp = tid >> 5;
    const int bm   = blockIdx.y * 128, bn = blockIdx.x * 128;
    const int K2   = Kd >> 1;
    const int wm   = (warp >> 2) * 64;    // 0 / 64
    const int wn   = (warp & 3) * 32;     // 0,32,64,96
    const int g    = lane >> 2, tg = lane & 3;

    const uint32_t sb = smem_u32(sm);

    // ldmatrix byte offsets within a tile, per ks (16-elem sub-chunk)
    const int arow = wm + (lane & 15);
    const int ahi  = lane >> 4;           // 0/1: k-halves
    const int axor = (arow >> 1) & 3;
    uint32_t aoff[2];
#pragma unroll
    for (int ks = 0; ks < 2; ks++)
        aoff[ks] = (uint32_t)(arow * 64 + (((ks*2 + ahi) ^ axor) << 4));
    const int bsel = (lane >> 3) & 1;
    const int brow = wn + (lane & 7) + (lane >> 4) * 8;
    uint32_t boff[2][2];  // [pr][ks]
#pragma unroll
    for (int pr = 0; pr < 2; pr++) {
        const int br = brow + pr * 16;
        const int bxor = (br >> 1) & 3;
#pragma unroll
        for (int ks = 0; ks < 2; ks++)
            boff[pr][ks] = (uint32_t)(br * 64 + (((ks*2 + bsel) ^ bxor) << 4));
    }

    // store-side mapping: slot = tid + it*256 -> row = tid/4 + it*64, q = tid&3
    const int q    = tid & 3;
    const int row0 = tid >> 2;
    int srow[2]; uint32_t soff[2];
#pragma unroll
    for (int it = 0; it < 2; it++) {
        srow[it] = row0 + it * 64;
        soff[it] = (uint32_t)(srow[it] * 16 + ((q ^ ((srow[it] >> 1) & 3)) << 2));
    }

    float acc[4][4][4];
#pragma unroll
    for (int i = 0; i < 4; i++)
#pragma unroll
        for (int j = 0; j < 4; j++)
#pragma unroll
            for (int c = 0; c < 4; c++) acc[i][j][c] = 0.f;

    const uint32_t* gs[3] = {AH, AL, WF};
    const uint4 z4 = make_uint4(0u, 0u, 0u, 0u);
    uint4 pv[3][2];

    // prefetch chunk 0
#pragma unroll
    for (int t = 0; t < 3; t++) {
        const int r0 = (t < 2) ? bm : bn;
        const bool isA = (t < 2);
#pragma unroll
        for (int it = 0; it < 2; it++) {
            const int r = srow[it];
            pv[t][it] = (isA || (bn + r) < N)
                ? *(const uint4*)(gs[t] + (size_t)(r0 + r) * K2 + q * 4) : z4;
        }
    }

    for (int kp0 = 0; kp0 < K2; kp0 += 16) {
        __syncthreads();
#pragma unroll
        for (int t = 0; t < 3; t++)
#pragma unroll
            for (int it = 0; it < 2; it++)
                *(uint4*)&sm[t][soff[it]] = pv[t][it];
        __syncthreads();

        if (kp0 + 16 < K2) {
#pragma unroll
            for (int t = 0; t < 3; t++) {
                const int r0 = (t < 2) ? bm : bn;
                const bool isA = (t < 2);
#pragma unroll
                for (int it = 0; it < 2; it++) {
                    const int r = srow[it];
                    pv[t][it] = (isA || (bn + r) < N)
                        ? *(const uint4*)(gs[t] + (size_t)(r0 + r) * K2 + kp0 + 16 + q * 4) : z4;
                }
            }
        }

#pragma unroll
        for (int ks = 0; ks < 2; ks++) {
            uint32_t aH4[4][4], aL4[4][4];
#pragma unroll
            for (int mt = 0; mt < 4; mt++) {
                ldsm4(aH4[mt], sb         + aoff[ks] + mt * 1024u);
                ldsm4(aL4[mt], sb + 8192u + aoff[ks] + mt * 1024u);
            }
#pragma unroll
            for (int pr = 0; pr < 2; pr++) {
                uint32_t bW4[4];
                ldsm4(bW4, sb + 16384u + boff[pr][ks]);
#pragma unroll
                for (int nt2 = 0; nt2 < 2; nt2++) {
                    const int nt = pr * 2 + nt2;
#pragma unroll
                    for (int mt = 0; mt < 4; mt++) {
                        mma_f16(acc[mt][nt], aH4[mt], &bW4[nt2*2]);
                        mma_f16(acc[mt][nt], aL4[mt], &bW4[nt2*2]);
                    }
                }
            }
        }
    }

    // epilogue
#pragma unroll
    for (int mt = 0; mt < 4; mt++) {
#pragma unroll
        for (int nt = 0; nt < 4; nt++) {
            const int r = bm + wm + mt*16 + g;
            const int c = bn + wn + nt*8 + tg*2;
            if (c < N) {
                float v[4] = {acc[mt][nt][0], acc[mt][nt][1],
                              acc[mt][nt][2], acc[mt][nt][3]};
                if (EPI == 1) {
                    const float b0 = bias[c], b1 = bias[c+1];
                    v[0] += b0; v[1] += b1; v[2] += b0; v[3] += b1;
#pragma unroll
                    for (int i = 0; i < 4; i++)
                        v[i] = 0.5f * v[i] * (1.f + erff(v[i] * 0.70710678118654752f));
                }
                if (EPI == 2) {
                    const float* r0p = res + (size_t)r * N + c;
                    const float* r1p = res + (size_t)(r+8) * N + c;
                    v[0] += r0p[0]; v[1] += r0p[1]; v[2] += r1p[0]; v[3] += r1p[1];
                }
                *(float2*)(C + (size_t)r     * N + c) = make_float2(v[0], v[1]);
                *(float2*)(C + (size_t)(r+8) * N + c) = make_float2(v[2], v[3]);
            }
        }
    }
}

// ---------------- LayerNorm (512) -> packed fp16 hi/lo -------------------------
__global__ __launch_bounds__(256) void ln_k(
    const float* __restrict__ x, const float* __restrict__ w,
    const float* __restrict__ b, uint32_t* __restrict__ uH,
    uint32_t* __restrict__ uL)
{
    __shared__ float red[256];
    const int row = blockIdx.x;
    const int tid = threadIdx.x;
    const float2 v = ((const float2*)(x + (size_t)row * D_))[tid];

    red[tid] = v.x + v.y;
    __syncthreads();
    for (int st = 128; st > 0; st >>= 1) {
        if (tid < st) red[tid] += red[tid + st];
        __syncthreads();
    }
    const float mean = red[0] * (1.f / D_);
    __syncthreads();
    const float d0 = v.x - mean, d1 = v.y - mean;
    red[tid] = d0*d0 + d1*d1;
    __syncthreads();
    for (int st = 128; st > 0; st >>= 1) {
        if (tid < st) red[tid] += red[tid + st];
        __syncthreads();
    }
    const float rstd = rsqrtf(red[0] * (1.f / D_) + 1e-5f);
    const float2 wv = ((const float2*)w)[tid];
    const float2 bv = ((const float2*)b)[tid];
    uint32_t H, L;
    pack_hl16(d0 * rstd * wv.x + bv.x, d1 * rstd * wv.y + bv.y, H, L);
    uH[(size_t)row * (D_/2) + tid] = H;
    uL[(size_t)row * (D_/2) + tid] = L;
}

// ---------------- causal depthwise conv (K=4) + SiLU ---------------------------
__global__ void conv_k(const float* __restrict__ zx, const float* __restrict__ w,
                       const float* __restrict__ bias, float* __restrict__ out)
{
    const int idx = blockIdx.x * blockDim.x + threadIdx.x;
    if (idx >= M_ * CD) return;
    const int c = idx % CD;
    const int m = idx / CD;
    const int t = m % L_;
    float acc = bias[c];
#pragma unroll
    for (int k = 0; k < KC; k++) {
        const int tt = t + k - (KC - 1);
        if (tt >= 0)
            acc = fmaf(zx[(size_t)(m + k - (KC-1)) * DP + DI + c], w[c*KC + k], acc);
    }
    out[idx] = silu_f(acc);
}

// ---------------- dt = softplus(dt+bias); dA = exp(dt * -exp(A_log)) -----------
__global__ void dt_k(const float* __restrict__ zx, const float* __restrict__ dtb,
                     const float* __restrict__ Alog,
                     float* __restrict__ dt, float* __restrict__ dA)
{
    const int idx = blockIdx.x * blockDim.x + threadIdx.x;
    if (idx >= M_ * NH) return;
    const int hh = idx % NH;
    const int m  = idx / NH;
    const float v = zx[(size_t)m * DP + DI + CD + hh] + dtb[hh];
    const float sp = (v > 20.f) ? v : log1pf(expf(v));
    dt[idx] = sp;
    dA[idx] = expf(sp * -expf(Alog[hh]));
}

// ---------------- sequential SSM scan (1 sync / step, double-buffered) ---------
__global__ __launch_bounds__(256) void scan_k(
    const float* __restrict__ xbc, const float* __restrict__ dt,
    const float* __restrict__ dA, const float* __restrict__ Dp,
    float* __restrict__ y)
{
    __shared__ float shB[2][DS], shC[2][DS], shX[2][32], red[2][256];
    const int psplit = blockIdx.x;
    const int h  = blockIdx.y;
    const int b  = blockIdx.z;
    const int tid = threadIdx.x;
    const int plocal = tid & 31;
    const int ngrp = tid >> 5;
    const int n0 = ngrp * 16;
    const int pg = psplit * 32 + plocal;
    const float Dv = Dp[h];

    float s[16];
#pragma unroll
    for (int j = 0; j < 16; j++) s[j] = 0.f;

    const size_t base = (size_t)b * L_;

    // load t=0, stage into sh[0]
    {
        const float* p = xbc + base * CD;
        if (tid < DS) shB[0][tid] = p[DI + tid];
        else          shC[0][tid - DS] = p[DI + DS + (tid - DS)];
        if (tid < 32) shX[0][tid] = p[h*HD + pg];
    }
    // prefetch t=1 into regs
    float rB = 0.f, rC = 0.f, rX = 0.f;
    {
        const float* p = xbc + (base + 1) * CD;
        if (tid < DS) rB = p[DI + tid];
        else          rC = p[DI + DS + (tid - DS)];
        if (tid < 32) rX = p[h*HD + pg];
    }
    float rdA = dA[base*NH + h];
    float rdt = dt[base*NH + h];
    __syncthreads();

    for (int t = 0; t < L_; t++) {
        const int cur = t & 1, nxt = cur ^ 1;
        const float dAv = rdA, dtv = rdt;

        // compute step t from sh[cur]
        const float a = dtv * shX[cur][plocal];
        float part = 0.f;
#pragma unroll
        for (int j = 0; j < 16; j++) {
            s[j] = fmaf(s[j], dAv, a * shB[cur][n0 + j]);
            part = fmaf(s[j], shC[cur][n0 + j], part);
        }
        red[cur][ngrp*32 + plocal] = part;

        // stage t+1 into sh[nxt]
        if (t + 1 < L_) {
            if (tid < DS) shB[nxt][tid] = rB;
            else          shC[nxt][tid - DS] = rC;
            if (tid < 32) shX[nxt][tid] = rX;
            rdA = dA[(base + t + 1)*NH + h];
            rdt = dt[(base + t + 1)*NH + h];
        }
        // prefetch t+2 into regs
        if (t + 2 < L_) {
            const float* p = xbc + (base + t + 2) * CD;
            if (tid < DS) rB = p[DI + tid];
            else          rC = p[DI + DS + (tid - DS)];
            if (tid < 32) rX = p[h*HD + pg];
        }

        __syncthreads();

        if (tid < 32) {
            float acc = shX[cur][tid] * Dv;
#pragma unroll
            for (int g2 = 0; g2 < 8; g2++) acc += red[cur][g2*32 + tid];
            y[(base + t)*DI + h*HD + pg] = acc;
        }
    }
}

// ---------------- gating + RMSNorm -> packed fp16 hi/lo ------------------------
__global__ __launch_bounds__(256) void gate_k(
    const float* __restrict__ zx, const float* __restrict__ gw,
    const float* __restrict__ y, uint32_t* __restrict__ yH,
    uint32_t* __restrict__ yL)
{
    __shared__ float red[256];
    const int row = blockIdx.x;
    const int tid = threadIdx.x;
    const float2* zr = (const float2*)(zx + (size_t)row * DP);
    const float2* yr = (const float2*)(y + (size_t)row * DI);
    float g0[2], g1[2]; float ss = 0.f;
#pragma unroll
    for (int i = 0; i < 2; i++) {
        const int p = tid + i*256;
        const float2 z2 = zr[p];
        const float2 y2 = yr[p];
        const float a = y2.x * silu_f(z2.x);
        const float b = y2.y * silu_f(z2.y);
        g0[i] = a; g1[i] = b; ss += a*a + b*b;
    }
    red[tid] = ss;
    __syncthreads();
    for (int st = 128; st > 0; st >>= 1) {
        if (tid < st) red[tid] += red[tid + st];
        __syncthreads();
    }
    const float scale = rsqrtf(red[0] * (1.f / DI) + 1e-5f);
#pragma unroll
    for (int i = 0; i < 2; i++) {
        const int p = tid + i*256;
        const float2 gv = ((const float2*)gw)[p];
        uint32_t H, L;
        pack_hl16(g0[i] * scale * gv.x, g1[i] * scale * gv.y, H, L);
        yH[(size_t)row * (DI/2) + p] = H;
        yL[(size_t)row * (DI/2) + p] = L;
    }
}

// ---------------- classifier ---------------------------------------------------
__global__ void cls_k(const float* __restrict__ h, const float* __restrict__ w,
                      const float* __restrict__ b, float* __restrict__ out)
{
    const int gwarp = (blockIdx.x * blockDim.x + threadIdx.x) >> 5;
    const int lane = threadIdx.x & 31;
    if (gwarp >= M_) return;
    const float* hr = h + (size_t)gwarp * D_;
    float a0 = 0.f, a1 = 0.f;
    for (int k = lane; k < D_; k += 32) {
        const float hv = hr[k];
        a0 = fmaf(hv, w[k],      a0);
        a1 = fmaf(hv, w[D_ + k], a1);
    }
    for (int off = 16; off; off >>= 1) {
        a0 += __shfl_xor_sync(0xFFFFFFFFu, a0, off);
        a1 += __shfl_xor_sync(0xFFFFFFFFu, a1, off);
    }
    if (lane == 0) {
        out[gwarp*2 + 0] = a0 + b[0];
        out[gwarp*2 + 1] = a1 + b[1];
    }
}

// ---------------- launch -------------------------------------------------------
extern "C" void kernel_launch(void* const* d_in, const int* in_sizes, int n_in,
                              void* d_out, int out_size)
{
    const float* x      = (const float*)d_in[0];
    const float* fc1_w  = (const float*)d_in[1];
    const float* fc1_b  = (const float*)d_in[2];
    const float* ln_w   = (const float*)d_in[3];
    const float* ln_b   = (const float*)d_in[4];
    const float* in_w   = (const float*)d_in[5];
    const float* conv_w = (const float*)d_in[6];
    const float* conv_b = (const float*)d_in[7];
    const float* dt_b   = (const float*)d_in[8];
    const float* A_log  = (const float*)d_in[9];
    const float* D_p    = (const float*)d_in[10];
    const float* gn_w   = (const float*)d_in[11];
    const float* out_w  = (const float*)d_in[12];
    const float* cls_w  = (const float*)d_in[13];
    const float* cls_b  = (const float*)d_in[14];
    float* out = (float*)d_out;

    float *h, *zx, *xbc, *dtp, *dAp, *y;
    uint32_t *xH, *xL, *uH, *uL, *yH, *yL;
    uint32_t *w1F, *wiF, *woF;
    cudaGetSymbolAddress((void**)&h,   g_h);
    cudaGetSymbolAddress((void**)&zx,  g_zx);
    cudaGetSymbolAddress((void**)&xbc, g_xbc);
    cudaGetSymbolAddress((void**)&dtp, g_dt);
    cudaGetSymbolAddress((void**)&dAp, g_dA);
    cudaGetSymbolAddress((void**)&y,   g_y);
    cudaGetSymbolAddress((void**)&xH,  g_xH);
    cudaGetSymbolAddress((void**)&xL,  g_xL);
    cudaGetSymbolAddress((void**)&uH,  g_uH);
    cudaGetSymbolAddress((void**)&uL,  g_uL);
    cudaGetSymbolAddress((void**)&yH,  g_yH);
    cudaGetSymbolAddress((void**)&yL,  g_yL);
    cudaGetSymbolAddress((void**)&w1F, g_w1F);
    cudaGetSymbolAddress((void**)&wiF, g_wiF);
    cudaGetSymbolAddress((void**)&woF, g_woF);

    // weight + input conversions (cheap, memory-bound)
    { int n = D_*IN_/2;      cvt_w<<<(n+255)/256, 256>>>(fc1_w, w1F, n); }
    { int n = NL*DP*D_/2;    cvt_w<<<(n+255)/256, 256>>>(in_w,  wiF, n); }
    { int n = NL*D_*DI/2;    cvt_w<<<(n+255)/256, 256>>>(out_w, woF, n); }
    { int n = M_*IN_/2;      cvt_a<<<(n+255)/256, 256>>>(x,     xH,  xL, n); }

    // fc1 + GELU
    gemm_ls<1><<<dim3(D_/128, M_/128), 256>>>(
        xH, xL, w1F, fc1_b, nullptr, h, M_, D_, IN_);

    for (int l = 0; l < NL; l++) {
        ln_k<<<M_, 256>>>(h, ln_w + l*D_, ln_b + l*D_, uH, uL);
        gemm_ls<0><<<dim3((DP + 127)/128, M_/128), 256>>>(
            uH, uL, wiF + (size_t)l*DP*(D_/2),
            nullptr, nullptr, zx, M_, DP, D_);
        conv_k<<<(M_*CD + 255)/256, 256>>>(zx, conv_w + l*CD*KC, conv_b + l*CD, xbc);
        dt_k<<<(M_*NH + 255)/256, 256>>>(zx, dt_b + l*NH, A_log + l*NH, dtp, dAp);
        scan_k<<<dim3(2, NH, B_), 256>>>(xbc, dtp, dAp, D_p + l*NH, y);
        gate_k<<<M_, 256>>>(zx, gn_w + l*DI, y, yH, yL);
        gemm_ls<2><<<dim3(D_/128, M_/128), 256>>>(
            yH, yL, woF + (size_t)l*D_*(DI/2),
            nullptr, h, h, M_, D_, DI);
    }

    cls_k<<<(M_*32 + 255)/256, 256>>>(h, cls_w, cls_b, out);
}